// round 14
// baseline (speedup 1.0000x reference)
#include <cuda_runtime.h>
#include <cuda_fp16.h>
#include <math.h>
#include <stdint.h>

#define N_TOK 2048
#define BATCH 2
#define DIM   1024
#define NHEAD 16
#define DHEAD 64
#define MROWS (BATCH * N_TOK)   // 4096
#define RMS_EPS 1.1920929e-07f

// ---------------- scratch (static __device__ — no allocation) ----------------
__device__ __half g_xh [MROWS * DIM];
__device__ __half g_xl [MROWS * DIM];
__device__ __half g_qh [MROWS * DIM], g_ql[MROWS * DIM];
__device__ __half g_kh [MROWS * DIM];
__device__ __half g_vh [MROWS * DIM];
__device__ __half g_aoh[MROWS * DIM];
__device__ __half g_aol[MROWS * DIM];
__device__ __half g_wq [DIM * DIM];
__device__ __half g_wk [DIM * DIM];
__device__ __half g_wv [DIM * DIM];
__device__ __half g_wo [DIM * DIM];
__device__ float g_cos[N_TOK * (DHEAD / 2)];
__device__ float g_sin[N_TOK * (DHEAD / 2)];

// ---------------- helpers ----------------------------------------------------
__device__ __forceinline__ uint32_t smem_u32(const void* p) {
    uint32_t a;
    asm("{ .reg .u64 t; cvta.to.shared.u64 t, %1; cvt.u32.u64 %0, t; }" : "=r"(a) : "l"(p));
    return a;
}
__device__ __forceinline__ void cp_async16(uint32_t dst, const void* src) {
    asm volatile("cp.async.cg.shared.global [%0], [%1], 16;" :: "r"(dst), "l"(src));
}
#define CP_COMMIT() asm volatile("cp.async.commit_group;" ::: "memory")
#define CP_WAIT0()  asm volatile("cp.async.wait_group 0;" ::: "memory")
#define CP_WAIT1()  asm volatile("cp.async.wait_group 1;" ::: "memory")

__device__ __forceinline__ void ldmatrix_x4(uint32_t& r0, uint32_t& r1,
                                            uint32_t& r2, uint32_t& r3, uint32_t addr) {
    asm volatile("ldmatrix.sync.aligned.m8n8.x4.shared.b16 {%0,%1,%2,%3}, [%4];"
                 : "=r"(r0), "=r"(r1), "=r"(r2), "=r"(r3) : "r"(addr));
}
__device__ __forceinline__ void ldmatrix_x4_trans(uint32_t& r0, uint32_t& r1,
                                                  uint32_t& r2, uint32_t& r3, uint32_t addr) {
    asm volatile("ldmatrix.sync.aligned.m8n8.x4.trans.shared.b16 {%0,%1,%2,%3}, [%4];"
                 : "=r"(r0), "=r"(r1), "=r"(r2), "=r"(r3) : "r"(addr));
}
__device__ __forceinline__ void mma_f16(float* d, const uint32_t* a, const uint32_t* b) {
    asm volatile(
        "mma.sync.aligned.m16n8k16.row.col.f32.f16.f16.f32 "
        "{%0,%1,%2,%3}, {%4,%5,%6,%7}, {%8,%9}, {%0,%1,%2,%3};"
        : "+f"(d[0]), "+f"(d[1]), "+f"(d[2]), "+f"(d[3])
        : "r"(a[0]), "r"(a[1]), "r"(a[2]), "r"(a[3]), "r"(b[0]), "r"(b[1]));
}
__device__ __forceinline__ uint32_t pack_h2(float lo, float hi) {
    __half2 h = __floats2half2_rn(lo, hi);       // lo -> low 16 bits
    return *reinterpret_cast<uint32_t*>(&h);
}
__device__ __forceinline__ void split2h(float x, __half& h, __half& l) {
    h = __float2half_rn(x);
    l = __float2half_rn(x - __half2float(h));
}
struct alignas(8) H4 { __half v[4]; };

// ---------------- RoPE cos/sin table (fp64 reduce + fp32 trig) ---------------
__global__ __launch_bounds__(256) void rope_table_kernel() {
    __shared__ float sinvf[32];
    if (threadIdx.x < 32)
        sinvf[threadIdx.x] = (float)pow(10000.0, -(double)(2 * threadIdx.x) / 64.0);
    __syncthreads();
    int idx = blockIdx.x * blockDim.x + threadIdx.x;   // t*32 + i
    if (idx >= N_TOK * 32) return;
    int t = idx >> 5;
    int i = idx & 31;
    float ang = (float)t * sinvf[i];
    double ad  = (double)ang;
    double k   = rint(ad * 0.15915494309189535);
    double red = ad - k * 6.283185307179586;
    float  rf  = (float)red;
    g_cos[idx] = cosf(rf);
    g_sin[idx] = sinf(rf);
}

// ---------------- RMSNorm fused with fp16 hi/lo split ------------------------
__global__ __launch_bounds__(256) void rmsnorm_split_kernel(
    const float* __restrict__ x, const float* __restrict__ w)
{
    int row = blockIdx.x;
    const float4* xr = (const float4*)(x + (size_t)row * DIM);
    float4 v4 = xr[threadIdx.x];
    float ss = v4.x * v4.x + v4.y * v4.y + v4.z * v4.z + v4.w * v4.w;
    #pragma unroll
    for (int o = 16; o; o >>= 1) ss += __shfl_xor_sync(0xFFFFFFFFu, ss, o);
    __shared__ float sred[8];
    int lane = threadIdx.x & 31, wid = threadIdx.x >> 5;
    if (lane == 0) sred[wid] = ss;
    __syncthreads();
    if (wid == 0) {
        float t = (lane < 8) ? sred[lane] : 0.f;
        #pragma unroll
        for (int o = 4; o; o >>= 1) t += __shfl_xor_sync(0xFFFFFFFFu, t, o);
        if (lane == 0) sred[0] = t;
    }
    __syncthreads();
    float scale = rsqrtf(sred[0] * (1.0f / (float)DIM) + RMS_EPS);
    float4 wv = ((const float4*)w)[threadIdx.x];
    float o0 = v4.x * scale * wv.x, o1 = v4.y * scale * wv.y;
    float o2 = v4.z * scale * wv.z, o3 = v4.w * scale * wv.w;
    H4 hb, lb;
    split2h(o0, hb.v[0], lb.v[0]); split2h(o1, hb.v[1], lb.v[1]);
    split2h(o2, hb.v[2], lb.v[2]); split2h(o3, hb.v[3], lb.v[3]);
    size_t base = (size_t)row * DIM + threadIdx.x * 4;
    *(H4*)&g_xh[base] = hb;
    *(H4*)&g_xl[base] = lb;
}

// ---------------- all 4 weights fp32 -> single fp16 (one launch) -------------
#define W4Q (DIM * DIM / 4)
__global__ __launch_bounds__(256) void split_w4_kernel(
    const float* __restrict__ w0, const float* __restrict__ w1,
    const float* __restrict__ w2, const float* __restrict__ w3,
    __half* __restrict__ h0, __half* __restrict__ h1,
    __half* __restrict__ h2, __half* __restrict__ h3)
{
    int idx  = blockIdx.x * blockDim.x + threadIdx.x;
    int wsel = idx >> 18;
    int j    = idx & (W4Q - 1);
    const float* w = (wsel == 0) ? w0 : (wsel == 1) ? w1 : (wsel == 2) ? w2 : w3;
    __half* wh = (wsel == 0) ? h0 : (wsel == 1) ? h1 : (wsel == 2) ? h2 : h3;
    float4 v4 = ((const float4*)w)[j];
    H4 hb;
    hb.v[0] = __float2half_rn(v4.x); hb.v[1] = __float2half_rn(v4.y);
    hb.v[2] = __float2half_rn(v4.z); hb.v[3] = __float2half_rn(v4.w);
    *(H4*)&wh[(size_t)j * 4] = hb;
}

// ---------------- HMMA fp16 2-pass NT GEMM (256 thr, 64x32 warp tiles) -------
#define KC      32
#define ROWB    80
#define OPTILE  (128 * ROWB)          // 10240
#define STAGEB  (3 * OPTILE)          // Ah, Al, Bh = 30720
#define GSMEM_DYN (2 * STAGEB)        // 61440
#define NCH     (DIM / KC)

__device__ __forceinline__ void load_stage(
    uint32_t sbase,
    const __half* __restrict__ Ah, const __half* __restrict__ Al,
    const __half* __restrict__ Bh,
    int bm, int bn, int kb, int tid)
{
    const __half* srcs[3] = { Ah, Al, Bh };
    #pragma unroll
    for (int op = 0; op < 3; op++) {
        int r0 = (op < 2) ? bm : bn;
        const __half* s = srcs[op];
        #pragma unroll
        for (int it = 0; it < 2; it++) {
            int i = tid + it * 256;     // 0..511
            int row = i >> 2, ch = i & 3;
            uint32_t dst = sbase + op * OPTILE + row * ROWB + ch * 16;
            cp_async16(dst, s + ((size_t)(r0 + row) * DIM + kb + ch * 8));
        }
    }
    CP_COMMIT();
}

__device__ __forceinline__ void gemm_mainloop(
    uint32_t sm0, int tid, int wid, int lane,
    const __half* __restrict__ Ah, const __half* __restrict__ Al,
    const __half* __restrict__ Bh,
    int bm, int bn, float acc[4][4][4])
{
    int wm = wid >> 2, wn = wid & 3;
    int arow = wm * 64 + (lane & 15);
    int akb  = (lane >> 4) * 16;
    int brow = wn * 32 + ((lane >> 4) * 8) + (lane & 7);
    int bkb  = ((lane >> 3) & 1) * 16;

    load_stage(sm0, Ah, Al, Bh, bm, bn, 0, tid);

    for (int c = 0; c < NCH; c++) {
        CP_WAIT0();
        __syncthreads();
        uint32_t sb = sm0 + (c & 1) * STAGEB;
        if (c + 1 < NCH)
            load_stage(sm0 + ((c + 1) & 1) * STAGEB, Ah, Al, Bh, bm, bn, (c + 1) * KC, tid);

        uint32_t sAh = sb, sAl = sb + OPTILE, sBh = sb + 2 * OPTILE;
        #pragma unroll
        for (int kk = 0; kk < 2; kk++) {
            // all fragments up front (no register reuse -> no WAR serialization)
            uint32_t ah[4][4], al[4][4], bh[4][2];
            #pragma unroll
            for (int mt = 0; mt < 4; mt++) {
                uint32_t ao = (uint32_t)((arow + mt * 16) * ROWB + kk * 32 + akb);
                ldmatrix_x4(ah[mt][0], ah[mt][1], ah[mt][2], ah[mt][3], sAh + ao);
            }
            #pragma unroll
            for (int mt = 0; mt < 4; mt++) {
                uint32_t ao = (uint32_t)((arow + mt * 16) * ROWB + kk * 32 + akb);
                ldmatrix_x4(al[mt][0], al[mt][1], al[mt][2], al[mt][3], sAl + ao);
            }
            #pragma unroll
            for (int p = 0; p < 2; p++) {
                uint32_t bo = (uint32_t)((brow + p * 16) * ROWB + kk * 32 + bkb);
                uint32_t r0, r1, r2, r3;
                ldmatrix_x4(r0, r1, r2, r3, sBh + bo);
                bh[p * 2][0] = r0; bh[p * 2][1] = r1; bh[p * 2 + 1][0] = r2; bh[p * 2 + 1][1] = r3;
            }
            // 32 MMAs as one uninterrupted stream
            #pragma unroll
            for (int mt = 0; mt < 4; mt++)
                #pragma unroll
                for (int nt = 0; nt < 4; nt++)
                    mma_f16(acc[mt][nt], ah[mt], bh[nt]);
            #pragma unroll
            for (int mt = 0; mt < 4; mt++)
                #pragma unroll
                for (int nt = 0; nt < 4; nt++)
                    mma_f16(acc[mt][nt], al[mt], bh[nt]);
        }
        __syncthreads();
    }
}

// ---------------- merged QKV projection GEMM (one launch) --------------------
__global__ __launch_bounds__(256, 2) void gemm_qkv(
    const __half* __restrict__ xh, const __half* __restrict__ xl,
    const __half* __restrict__ wq, const __half* __restrict__ wk,
    const __half* __restrict__ wv,
    __half* __restrict__ qh, __half* __restrict__ ql,
    __half* __restrict__ kh, __half* __restrict__ vh)
{
    extern __shared__ char smem[];
    uint32_t sm0 = smem_u32(smem);
    int tid = threadIdx.x, wid = tid >> 5, lane = tid & 31;
    int g  = blockIdx.x >> 3;
    int bn = (blockIdx.x & 7) * 128;
    int bm = blockIdx.y * 128;

    const __half* Bh = (g == 0) ? wq : (g == 1) ? wk : wv;
    float qscale = (g == 0) ? 0.125f : 1.0f;

    float acc[4][4][4];
    #pragma unroll
    for (int i = 0; i < 4; i++)
        #pragma unroll
        for (int j = 0; j < 4; j++)
            #pragma unroll
            for (int e = 0; e < 4; e++) acc[i][j][e] = 0.f;

    gemm_mainloop(sm0, tid, wid, lane, xh, xl, Bh, bm, bn, acc);

    int wm = wid >> 2, wn = wid & 3;
    int r = lane >> 2, cp = (lane & 3) * 2;
    #pragma unroll
    for (int mt = 0; mt < 4; mt++) {
        int gm = bm + wm * 64 + mt * 16 + r;
        #pragma unroll
        for (int nt = 0; nt < 4; nt++) {
            int gc = bn + wn * 32 + nt * 8 + cp;
            float a0 = acc[mt][nt][0], a1 = acc[mt][nt][1];
            float a2 = acc[mt][nt][2], a3 = acc[mt][nt][3];
            if (g < 2) {   // RoPE (+ q scale)
                int i = (gc >> 1) & 31;
                int pos0 = gm & (N_TOK - 1);
                float c0 = g_cos[pos0 * 32 + i], s0 = g_sin[pos0 * 32 + i];
                float e = (a0 * c0 - a1 * s0) * qscale;
                float o = (a1 * c0 + a0 * s0) * qscale;
                a0 = e; a1 = o;
                int pos1 = (gm + 8) & (N_TOK - 1);
                float c1 = g_cos[pos1 * 32 + i], s1 = g_sin[pos1 * 32 + i];
                e = (a2 * c1 - a3 * s1) * qscale;
                o = (a3 * c1 + a2 * s1) * qscale;
                a2 = e; a3 = o;
            }
            size_t o0 = (size_t)gm * DIM + gc;
            size_t o1 = (size_t)(gm + 8) * DIM + gc;
            if (g == 0) {          // q: split hi/lo
                __half h0, l0, h1, l1;
                split2h(a0, h0, l0); split2h(a1, h1, l1);
                *(__half2*)(qh + o0) = __halves2half2(h0, h1);
                *(__half2*)(ql + o0) = __halves2half2(l0, l1);
                split2h(a2, h0, l0); split2h(a3, h1, l1);
                *(__half2*)(qh + o1) = __halves2half2(h0, h1);
                *(__half2*)(ql + o1) = __halves2half2(l0, l1);
            } else if (g == 1) {   // k: single fp16
                *(__half2*)(kh + o0) = __floats2half2_rn(a0, a1);
                *(__half2*)(kh + o1) = __floats2half2_rn(a2, a3);
            } else {               // v: single fp16
                *(__half2*)(vh + o0) = __floats2half2_rn(a0, a1);
                *(__half2*)(vh + o1) = __floats2half2_rn(a2, a3);
            }
        }
    }
}

// ---------------- output projection GEMM (fp32 epilogue) ---------------------
__global__ __launch_bounds__(256, 2) void gemm_out(
    const __half* __restrict__ Ah, const __half* __restrict__ Al,
    const __half* __restrict__ Bh, float* __restrict__ C)
{
    extern __shared__ char smem[];
    uint32_t sm0 = smem_u32(smem);
    int tid = threadIdx.x, wid = tid >> 5, lane = tid & 31;
    int bm = blockIdx.y * 128, bn = blockIdx.x * 128;

    float acc[4][4][4];
    #pragma unroll
    for (int i = 0; i < 4; i++)
        #pragma unroll
        for (int j = 0; j < 4; j++)
            #pragma unroll
            for (int e = 0; e < 4; e++) acc[i][j][e] = 0.f;

    gemm_mainloop(sm0, tid, wid, lane, Ah, Al, Bh, bm, bn, acc);

    int wm = wid >> 2, wn = wid & 3;
    int r = lane >> 2, cp = (lane & 3) * 2;
    #pragma unroll
    for (int mt = 0; mt < 4; mt++) {
        int gm = bm + wm * 64 + mt * 16 + r;
        #pragma unroll
        for (int nt = 0; nt < 4; nt++) {
            int gc = bn + wn * 32 + nt * 8 + cp;
            *(float2*)(C + (size_t)gm * DIM + gc)       = make_float2(acc[mt][nt][0], acc[mt][nt][1]);
            *(float2*)(C + (size_t)(gm + 8) * DIM + gc) = make_float2(acc[mt][nt][2], acc[mt][nt][3]);
        }
    }
}

// ---------------- HMMA fp16 2-pass causal flash attention --------------------
// 256 threads, 8 warps; CTA covers 128 q rows sharing each 64-key K/V stage.
#define FROW   144
#define FTILE  (64 * FROW)            // 9216
#define FSTAGE (2 * FTILE)            // 18432 (Kh, Vh)
#define FQOFF  (2 * FSTAGE)           // 36864
#define QTILE  (128 * FROW)           // 18432
#define FSMEM  (FQOFF + 2 * QTILE)    // 73728

__device__ __forceinline__ void flash_load_kv(
    uint32_t sbase,
    const __half* __restrict__ kh, const __half* __restrict__ vh,
    int grow0, int h, int tid)
{
    const __half* srcs[2] = { kh, vh };
    #pragma unroll
    for (int t = 0; t < 4; t++) {
        int i = tid + t * 256;          // 0..1023
        int tile = i >> 9;
        int r = (i >> 3) & 63;
        int ch = i & 7;
        uint32_t dst = sbase + tile * FTILE + r * FROW + ch * 16;
        cp_async16(dst, srcs[tile] + ((size_t)(grow0 + r) * DIM + h * DHEAD + ch * 8));
    }
}

__global__ __launch_bounds__(256) void flash_tc(
    const __half* __restrict__ Qh, const __half* __restrict__ Ql,
    const __half* __restrict__ Kh, const __half* __restrict__ Vh,
    __half* __restrict__ Oh, __half* __restrict__ Ol)
{
    extern __shared__ char smem[];
    uint32_t sm0 = smem_u32(smem);
    int tid = threadIdx.x, w = tid >> 5, lane = tid & 31;
    int bh = blockIdx.x;
    int b  = bh >> 4, h = bh & 15;
    int r0 = ((int)gridDim.y - 1 - (int)blockIdx.y) * 128;   // 128 q rows per CTA
    int ntiles = r0 / 64 + 2;
    int growq = b * N_TOK + r0;

    {   // Q (128 rows, hi/lo) + KV stage 0, then KV stage 1
        const __half* qs[2] = { Qh, Ql };
        #pragma unroll
        for (int t = 0; t < 8; t++) {
            int i = tid + t * 256;      // 0..2047
            int hl = i >> 10;
            int r = (i >> 3) & 127;
            int ch = i & 7;
            uint32_t dst = sm0 + FQOFF + hl * QTILE + r * FROW + ch * 16;
            cp_async16(dst, qs[hl] + ((size_t)(growq + r) * DIM + h * DHEAD + ch * 8));
        }
        flash_load_kv(sm0, Kh, Vh, b * N_TOK, h, tid);
        CP_COMMIT();
        flash_load_kv(sm0 + FSTAGE, Kh, Vh, b * N_TOK + 64, h, tid);
        CP_COMMIT();
    }

    uint32_t qhf[4][4], qlf[4][4];
    float oacc[8][4];
    #pragma unroll
    for (int nt = 0; nt < 8; nt++)
        #pragma unroll
        for (int e = 0; e < 4; e++) oacc[nt][e] = 0.f;
    float m0 = -1e30f, m1 = -1e30f, l0 = 0.f, l1 = 0.f;
    int wmin = r0 + w * 16;             // this warp's MIN q row (mask gate)

    for (int t = 0; t < ntiles; t++) {
        if (t + 1 < ntiles) { CP_WAIT1(); } else { CP_WAIT0(); }
        __syncthreads();

        if (t == 0) {   // Q fragments (once); warp w covers q rows w*16..w*16+15
            uint32_t qb = sm0 + FQOFF + (uint32_t)((w * 16 + (lane & 15)) * FROW + (lane >> 4) * 16);
            #pragma unroll
            for (int kt = 0; kt < 4; kt++) {
                ldmatrix_x4(qhf[kt][0], qhf[kt][1], qhf[kt][2], qhf[kt][3], qb + kt * 32);
                ldmatrix_x4(qlf[kt][0], qlf[kt][1], qlf[kt][2], qlf[kt][3], qb + QTILE + kt * 32);
            }
        }

        uint32_t sb = sm0 + (uint32_t)(t & 1) * FSTAGE;

        float sacc[8][4];
        #pragma unroll
        for (int nt = 0; nt < 8; nt++)
            #pragma unroll
            for (int e = 0; e < 4; e++) sacc[nt][e] = 0.f;

        uint32_t kb = sb + (uint32_t)(((lane & 7) + ((lane >> 4) & 1) * 8) * FROW + ((lane >> 3) & 1) * 16);
        #pragma unroll
        for (int kt = 0; kt < 4; kt++)
            #pragma unroll
            for (int jg = 0; jg < 4; jg++) {
                uint32_t addr = kb + (uint32_t)(jg * 16 * FROW + kt * 32);
                uint32_t bhh[4];
                ldmatrix_x4(bhh[0], bhh[1], bhh[2], bhh[3], addr);
                mma_f16(sacc[2 * jg],     qhf[kt], &bhh[0]);
                mma_f16(sacc[2 * jg],     qlf[kt], &bhh[0]);
                mma_f16(sacc[2 * jg + 1], qhf[kt], &bhh[2]);
                mma_f16(sacc[2 * jg + 1], qlf[kt], &bhh[2]);
            }

        if (t * 64 + 63 > wmin) {   // mask any tile whose keys can exceed this warp's rows
            int i0 = r0 + w * 16 + (lane >> 2);
            int j0 = t * 64 + (lane & 3) * 2;
            #pragma unroll
            for (int nt = 0; nt < 8; nt++) {
                int jc = j0 + nt * 8;
                if (jc     > i0)     sacc[nt][0] = -1e30f;
                if (jc + 1 > i0)     sacc[nt][1] = -1e30f;
                if (jc     > i0 + 8) sacc[nt][2] = -1e30f;
                if (jc + 1 > i0 + 8) sacc[nt][3] = -1e30f;
            }
        }

        float mx0 = -1e30f, mx1 = -1e30f;
        #pragma unroll
        for (int nt = 0; nt < 8; nt++) {
            mx0 = fmaxf(mx0, fmaxf(sacc[nt][0], sacc[nt][1]));
            mx1 = fmaxf(mx1, fmaxf(sacc[nt][2], sacc[nt][3]));
        }
        mx0 = fmaxf(mx0, __shfl_xor_sync(0xFFFFFFFFu, mx0, 1));
        mx0 = fmaxf(mx0, __shfl_xor_sync(0xFFFFFFFFu, mx0, 2));
        mx1 = fmaxf(mx1, __shfl_xor_sync(0xFFFFFFFFu, mx1, 1));
        mx1 = fmaxf(mx1, __shfl_xor_sync(0xFFFFFFFFu, mx1, 2));
        float mn0 = fmaxf(m0, mx0), mn1 = fmaxf(m1, mx1);
        float sc0 = __expf(m0 - mn0), sc1 = __expf(m1 - mn1);
        l0 *= sc0; l1 *= sc1;
        #pragma unroll
        for (int nt = 0; nt < 8; nt++) {
            oacc[nt][0] *= sc0; oacc[nt][1] *= sc0;
            oacc[nt][2] *= sc1; oacc[nt][3] *= sc1;
        }
        float su0 = 0.f, su1 = 0.f;
        #pragma unroll
        for (int nt = 0; nt < 8; nt++) {
            float p0 = __expf(sacc[nt][0] - mn0);
            float p1 = __expf(sacc[nt][1] - mn0);
            float p2 = __expf(sacc[nt][2] - mn1);
            float p3 = __expf(sacc[nt][3] - mn1);
            sacc[nt][0] = p0; sacc[nt][1] = p1; sacc[nt][2] = p2; sacc[nt][3] = p3;
            su0 += p0 + p1; su1 += p2 + p3;
        }
        su0 += __shfl_xor_sync(0xFFFFFFFFu, su0, 1);
        su0 += __shfl_xor_sync(0xFFFFFFFFu, su0, 2);
        su1 += __shfl_xor_sync(0xFFFFFFFFu, su1, 1);
        su1 += __shfl_xor_sync(0xFFFFFFFFu, su1, 2);
        l0 += su0; l1 += su1;
        m0 = mn0; m1 = mn1;

        uint32_t vb = sb + FTILE
                    + (uint32_t)(((lane & 7) + ((lane >> 3) & 1) * 8) * FROW + ((lane >> 4) & 1) * 16);
        #pragma unroll
        for (int kt = 0; kt < 4; kt++) {
            int t0 = 2 * kt, t1 = 2 * kt + 1;
            float ph[8], pl[8];
            #pragma unroll
            for (int e = 0; e < 4; e++) {
                float p = sacc[t0][e];
                float hh = __half2float(__float2half_rn(p));
                ph[e] = hh; pl[e] = p - hh;
                p = sacc[t1][e];
                hh = __half2float(__float2half_rn(p));
                ph[4 + e] = hh; pl[4 + e] = p - hh;
            }
            uint32_t pa_h[4], pa_l[4];
            pa_h[0] = pack_h2(ph[0], ph[1]); pa_h[1] = pack_h2(ph[2], ph[3]);
            pa_h[2] = pack_h2(ph[4], ph[5]); pa_h[3] = pack_h2(ph[6], ph[7]);
            pa_l[0] = pack_h2(pl[0], pl[1]); pa_l[1] = pack_h2(pl[2], pl[3]);
            pa_l[2] = pack_h2(pl[4], pl[5]); pa_l[3] = pack_h2(pl[6], pl[7]);

            #pragma unroll
            for (int dp = 0; dp < 4; dp++) {
                uint32_t addr = vb + (uint32_t)(kt * 16 * FROW + dp * 32);
                uint32_t vhh[4];
                ldmatrix_x4_trans(vhh[0], vhh[1], vhh[2], vhh[3], addr);
                mma_f16(oacc[2 * dp],     pa_h, &vhh[0]);
                mma_f16(oacc[2 * dp],     pa_l, &vhh[0]);
                mma_f16(oacc[2 * dp + 1], pa_h, &vhh[2]);
                mma_f16(oacc[2 * dp + 1], pa_l, &vhh[2]);
            }
        }

        __syncthreads();
        if (t + 2 < ntiles) {
            flash_load_kv(sm0 + (uint32_t)(t & 1) * FSTAGE, Kh, Vh,
                          b * N_TOK + (t + 2) * 64, h, tid);
            CP_COMMIT();
        }
    }

    float inv0 = 1.f / l0, inv1 = 1.f / l1;
    int gr = b * N_TOK + r0 + w * 16 + (lane >> 2);
    int gc = h * DHEAD + (lane & 3) * 2;
    #pragma unroll
    for (int nt = 0; nt < 8; nt++) {
        float a0 = oacc[nt][0] * inv0, a1 = oacc[nt][1] * inv0;
        float a2 = oacc[nt][2] * inv1, a3 = oacc[nt][3] * inv1;
        __half h0, lo0, h1, lo1;
        split2h(a0, h0, lo0); split2h(a1, h1, lo1);
        size_t o0 = (size_t)gr * DIM + gc + nt * 8;
        *(__half2*)&Oh[o0] = __halves2half2(h0, h1);
        *(__half2*)&Ol[o0] = __halves2half2(lo0, lo1);
        split2h(a2, h0, lo0); split2h(a3, h1, lo1);
        size_t o1 = (size_t)(gr + 8) * DIM + gc + nt * 8;
        *(__half2*)&Oh[o1] = __halves2half2(h0, h1);
        *(__half2*)&Ol[o1] = __halves2half2(lo0, lo1);
    }
}

// ---------------- launch -----------------------------------------------------
extern "C" void kernel_launch(void* const* d_in, const int* in_sizes, int n_in,
                              void* d_out, int out_size)
{
    const float* tokens = (const float*)d_in[0];
    const float* normw  = (const float*)d_in[1];
    const float* wq     = (const float*)d_in[2];
    const float* wk     = (const float*)d_in[3];
    const float* wv     = (const float*)d_in[4];
    const float* wo     = (const float*)d_in[5];
    float* out = (float*)d_out;

    __half *xh, *xl, *qh, *ql, *kh, *vh, *aoh, *aol;
    __half *pwq, *pwk, *pwv, *pwo;
    cudaGetSymbolAddress((void**)&xh,  g_xh);
    cudaGetSymbolAddress((void**)&xl,  g_xl);
    cudaGetSymbolAddress((void**)&qh,  g_qh);
    cudaGetSymbolAddress((void**)&ql,  g_ql);
    cudaGetSymbolAddress((void**)&kh,  g_kh);
    cudaGetSymbolAddress((void**)&vh,  g_vh);
    cudaGetSymbolAddress((void**)&aoh, g_aoh);
    cudaGetSymbolAddress((void**)&aol, g_aol);
    cudaGetSymbolAddress((void**)&pwq, g_wq);
    cudaGetSymbolAddress((void**)&pwk, g_wk);
    cudaGetSymbolAddress((void**)&pwv, g_wv);
    cudaGetSymbolAddress((void**)&pwo, g_wo);

    cudaFuncSetAttribute(gemm_qkv, cudaFuncAttributeMaxDynamicSharedMemorySize, GSMEM_DYN);
    cudaFuncSetAttribute(gemm_out, cudaFuncAttributeMaxDynamicSharedMemorySize, GSMEM_DYN);
    cudaFuncSetAttribute(flash_tc, cudaFuncAttributeMaxDynamicSharedMemorySize, FSMEM);

    rope_table_kernel<<<256, 256>>>();                                    // 1
    split_w4_kernel<<<4096, 256>>>(wq, wk, wv, wo, pwq, pwk, pwv, pwo);   // 2
    rmsnorm_split_kernel<<<MROWS, 256>>>(tokens, normw);                  // 3

    gemm_qkv<<<dim3(24, MROWS / 128), 256, GSMEM_DYN>>>(                  // 4
        xh, xl, pwq, pwk, pwv, qh, ql, kh, vh);

    flash_tc<<<dim3(BATCH * NHEAD, N_TOK / 128), 256, FSMEM>>>(           // 5
        qh, ql, kh, vh, aoh, aol);

    gemm_out<<<dim3(DIM / 128, MROWS / 128), 256, GSMEM_DYN>>>(           // 6
        aoh, aol, pwo, out);
}

// round 15
// speedup vs baseline: 1.5986x; 1.5986x over previous
#include <cuda_runtime.h>
#include <cuda_fp16.h>
#include <math.h>
#include <stdint.h>

#define N_TOK 2048
#define BATCH 2
#define DIM   1024
#define NHEAD 16
#define DHEAD 64
#define MROWS (BATCH * N_TOK)   // 4096
#define RMS_EPS 1.1920929e-07f

// ---------------- scratch (static __device__ — no allocation) ----------------
__device__ __half g_x  [MROWS * DIM];
__device__ __half g_q  [MROWS * DIM];
__device__ __half g_k  [MROWS * DIM];
__device__ __half g_v  [MROWS * DIM];
__device__ __half g_ao [MROWS * DIM];
__device__ __half g_wq [DIM * DIM];
__device__ __half g_wk [DIM * DIM];
__device__ __half g_wv [DIM * DIM];
__device__ __half g_wo [DIM * DIM];
__device__ float g_cos[N_TOK * (DHEAD / 2)];
__device__ float g_sin[N_TOK * (DHEAD / 2)];

// ---------------- helpers ----------------------------------------------------
__device__ __forceinline__ uint32_t smem_u32(const void* p) {
    uint32_t a;
    asm("{ .reg .u64 t; cvta.to.shared.u64 t, %1; cvt.u32.u64 %0, t; }" : "=r"(a) : "l"(p));
    return a;
}
__device__ __forceinline__ void cp_async16(uint32_t dst, const void* src) {
    asm volatile("cp.async.cg.shared.global [%0], [%1], 16;" :: "r"(dst), "l"(src));
}
#define CP_COMMIT() asm volatile("cp.async.commit_group;" ::: "memory")
#define CP_WAIT0()  asm volatile("cp.async.wait_group 0;" ::: "memory")
#define CP_WAIT1()  asm volatile("cp.async.wait_group 1;" ::: "memory")

__device__ __forceinline__ void ldmatrix_x4(uint32_t& r0, uint32_t& r1,
                                            uint32_t& r2, uint32_t& r3, uint32_t addr) {
    asm volatile("ldmatrix.sync.aligned.m8n8.x4.shared.b16 {%0,%1,%2,%3}, [%4];"
                 : "=r"(r0), "=r"(r1), "=r"(r2), "=r"(r3) : "r"(addr));
}
__device__ __forceinline__ void ldmatrix_x4_trans(uint32_t& r0, uint32_t& r1,
                                                  uint32_t& r2, uint32_t& r3, uint32_t addr) {
    asm volatile("ldmatrix.sync.aligned.m8n8.x4.trans.shared.b16 {%0,%1,%2,%3}, [%4];"
                 : "=r"(r0), "=r"(r1), "=r"(r2), "=r"(r3) : "r"(addr));
}
__device__ __forceinline__ void mma_f16(float* d, const uint32_t* a, const uint32_t* b) {
    asm volatile(
        "mma.sync.aligned.m16n8k16.row.col.f32.f16.f16.f32 "
        "{%0,%1,%2,%3}, {%4,%5,%6,%7}, {%8,%9}, {%0,%1,%2,%3};"
        : "+f"(d[0]), "+f"(d[1]), "+f"(d[2]), "+f"(d[3])
        : "r"(a[0]), "r"(a[1]), "r"(a[2]), "r"(a[3]), "r"(b[0]), "r"(b[1]));
}
__device__ __forceinline__ uint32_t pack_h2(float lo, float hi) {
    __half2 h = __floats2half2_rn(lo, hi);       // lo -> low 16 bits
    return *reinterpret_cast<uint32_t*>(&h);
}
struct alignas(8) H4 { __half v[4]; };

// ---------------- RoPE cos/sin table (fp64 reduce + fp32 trig) ---------------
__global__ __launch_bounds__(256) void rope_table_kernel() {
    __shared__ float sinvf[32];
    if (threadIdx.x < 32)
        sinvf[threadIdx.x] = (float)pow(10000.0, -(double)(2 * threadIdx.x) / 64.0);
    __syncthreads();
    int idx = blockIdx.x * blockDim.x + threadIdx.x;   // t*32 + i
    if (idx >= N_TOK * 32) return;
    int t = idx >> 5;
    int i = idx & 31;
    float ang = (float)t * sinvf[i];
    double ad  = (double)ang;
    double k   = rint(ad * 0.15915494309189535);
    double red = ad - k * 6.283185307179586;
    float  rf  = (float)red;
    g_cos[idx] = cosf(rf);
    g_sin[idx] = sinf(rf);
}

// ---------------- RMSNorm -> single fp16 --------------------------------------
__global__ __launch_bounds__(256) void rmsnorm_kernel(
    const float* __restrict__ x, const float* __restrict__ w)
{
    int row = blockIdx.x;
    const float4* xr = (const float4*)(x + (size_t)row * DIM);
    float4 v4 = xr[threadIdx.x];
    float ss = v4.x * v4.x + v4.y * v4.y + v4.z * v4.z + v4.w * v4.w;
    #pragma unroll
    for (int o = 16; o; o >>= 1) ss += __shfl_xor_sync(0xFFFFFFFFu, ss, o);
    __shared__ float sred[8];
    int lane = threadIdx.x & 31, wid = threadIdx.x >> 5;
    if (lane == 0) sred[wid] = ss;
    __syncthreads();
    if (wid == 0) {
        float t = (lane < 8) ? sred[lane] : 0.f;
        #pragma unroll
        for (int o = 4; o; o >>= 1) t += __shfl_xor_sync(0xFFFFFFFFu, t, o);
        if (lane == 0) sred[0] = t;
    }
    __syncthreads();
    float scale = rsqrtf(sred[0] * (1.0f / (float)DIM) + RMS_EPS);
    float4 wv = ((const float4*)w)[threadIdx.x];
    H4 hb;
    hb.v[0] = __float2half_rn(v4.x * scale * wv.x);
    hb.v[1] = __float2half_rn(v4.y * scale * wv.y);
    hb.v[2] = __float2half_rn(v4.z * scale * wv.z);
    hb.v[3] = __float2half_rn(v4.w * scale * wv.w);
    *(H4*)&g_x[(size_t)row * DIM + threadIdx.x * 4] = hb;
}

// ---------------- all 4 weights fp32 -> single fp16 (one launch) -------------
#define W4Q (DIM * DIM / 4)
__global__ __launch_bounds__(256) void split_w4_kernel(
    const float* __restrict__ w0, const float* __restrict__ w1,
    const float* __restrict__ w2, const float* __restrict__ w3,
    __half* __restrict__ h0, __half* __restrict__ h1,
    __half* __restrict__ h2, __half* __restrict__ h3)
{
    int idx  = blockIdx.x * blockDim.x + threadIdx.x;
    int wsel = idx >> 18;
    int j    = idx & (W4Q - 1);
    const float* w = (wsel == 0) ? w0 : (wsel == 1) ? w1 : (wsel == 2) ? w2 : w3;
    __half* wh = (wsel == 0) ? h0 : (wsel == 1) ? h1 : (wsel == 2) ? h2 : h3;
    float4 v4 = ((const float4*)w)[j];
    H4 hb;
    hb.v[0] = __float2half_rn(v4.x); hb.v[1] = __float2half_rn(v4.y);
    hb.v[2] = __float2half_rn(v4.z); hb.v[3] = __float2half_rn(v4.w);
    *(H4*)&wh[(size_t)j * 4] = hb;
}

// ---------------- HMMA fp16 1-pass NT GEMM (256 thr, 64x32 warp tiles) -------
#define KC      32
#define ROWB    80
#define OPTILE  (128 * ROWB)          // 10240
#define STAGEB  (2 * OPTILE)          // A, B = 20480
#define GSMEM_DYN (2 * STAGEB)        // 40960
#define NCH     (DIM / KC)

__device__ __forceinline__ void load_stage(
    uint32_t sbase,
    const __half* __restrict__ A, const __half* __restrict__ B,
    int bm, int bn, int kb, int tid)
{
    const __half* srcs[2] = { A, B };
    #pragma unroll
    for (int op = 0; op < 2; op++) {
        int r0 = (op == 0) ? bm : bn;
        const __half* s = srcs[op];
        #pragma unroll
        for (int it = 0; it < 2; it++) {
            int i = tid + it * 256;     // 0..511
            int row = i >> 2, ch = i & 3;
            uint32_t dst = sbase + op * OPTILE + row * ROWB + ch * 16;
            cp_async16(dst, s + ((size_t)(r0 + row) * DIM + kb + ch * 8));
        }
    }
    CP_COMMIT();
}

__device__ __forceinline__ void gemm_mainloop(
    uint32_t sm0, int tid, int wid, int lane,
    const __half* __restrict__ A, const __half* __restrict__ B,
    int bm, int bn, float acc[4][4][4])
{
    int wm = wid >> 2, wn = wid & 3;
    int arow = wm * 64 + (lane & 15);
    int akb  = (lane >> 4) * 16;
    int brow = wn * 32 + ((lane >> 4) * 8) + (lane & 7);
    int bkb  = ((lane >> 3) & 1) * 16;

    load_stage(sm0, A, B, bm, bn, 0, tid);

    for (int c = 0; c < NCH; c++) {
        CP_WAIT0();
        __syncthreads();
        uint32_t sb = sm0 + (c & 1) * STAGEB;
        if (c + 1 < NCH)
            load_stage(sm0 + ((c + 1) & 1) * STAGEB, A, B, bm, bn, (c + 1) * KC, tid);

        uint32_t sA = sb, sB = sb + OPTILE;
        #pragma unroll
        for (int kk = 0; kk < 2; kk++) {
            uint32_t ah[4][4], bh[4][2];
            #pragma unroll
            for (int mt = 0; mt < 4; mt++) {
                uint32_t ao = (uint32_t)((arow + mt * 16) * ROWB + kk * 32 + akb);
                ldmatrix_x4(ah[mt][0], ah[mt][1], ah[mt][2], ah[mt][3], sA + ao);
            }
            #pragma unroll
            for (int p = 0; p < 2; p++) {
                uint32_t bo = (uint32_t)((brow + p * 16) * ROWB + kk * 32 + bkb);
                uint32_t r0, r1, r2, r3;
                ldmatrix_x4(r0, r1, r2, r3, sB + bo);
                bh[p * 2][0] = r0; bh[p * 2][1] = r1; bh[p * 2 + 1][0] = r2; bh[p * 2 + 1][1] = r3;
            }
            #pragma unroll
            for (int mt = 0; mt < 4; mt++)
                #pragma unroll
                for (int nt = 0; nt < 4; nt++)
                    mma_f16(acc[mt][nt], ah[mt], bh[nt]);
        }
        __syncthreads();
    }
}

// ---------------- merged QKV projection GEMM (one launch) --------------------
__global__ __launch_bounds__(256, 2) void gemm_qkv(
    const __half* __restrict__ x,
    const __half* __restrict__ wq, const __half* __restrict__ wk,
    const __half* __restrict__ wv,
    __half* __restrict__ q, __half* __restrict__ k, __half* __restrict__ v)
{
    extern __shared__ char smem[];
    uint32_t sm0 = smem_u32(smem);
    int tid = threadIdx.x, wid = tid >> 5, lane = tid & 31;
    int g  = blockIdx.x >> 3;
    int bn = (blockIdx.x & 7) * 128;
    int bm = blockIdx.y * 128;

    const __half* B = (g == 0) ? wq : (g == 1) ? wk : wv;
    __half* C = (g == 0) ? q : (g == 1) ? k : v;
    float qscale = (g == 0) ? 0.125f : 1.0f;

    float acc[4][4][4];
    #pragma unroll
    for (int i = 0; i < 4; i++)
        #pragma unroll
        for (int j = 0; j < 4; j++)
            #pragma unroll
            for (int e = 0; e < 4; e++) acc[i][j][e] = 0.f;

    gemm_mainloop(sm0, tid, wid, lane, x, B, bm, bn, acc);

    int wm = wid >> 2, wn = wid & 3;
    int r = lane >> 2, cp = (lane & 3) * 2;
    #pragma unroll
    for (int mt = 0; mt < 4; mt++) {
        int gm = bm + wm * 64 + mt * 16 + r;
        #pragma unroll
        for (int nt = 0; nt < 4; nt++) {
            int gc = bn + wn * 32 + nt * 8 + cp;
            float a0 = acc[mt][nt][0], a1 = acc[mt][nt][1];
            float a2 = acc[mt][nt][2], a3 = acc[mt][nt][3];
            if (g < 2) {   // RoPE (+ q scale)
                int i = (gc >> 1) & 31;
                int pos0 = gm & (N_TOK - 1);
                float c0 = g_cos[pos0 * 32 + i], s0 = g_sin[pos0 * 32 + i];
                float e = (a0 * c0 - a1 * s0) * qscale;
                float o = (a1 * c0 + a0 * s0) * qscale;
                a0 = e; a1 = o;
                int pos1 = (gm + 8) & (N_TOK - 1);
                float c1 = g_cos[pos1 * 32 + i], s1 = g_sin[pos1 * 32 + i];
                e = (a2 * c1 - a3 * s1) * qscale;
                o = (a3 * c1 + a2 * s1) * qscale;
                a2 = e; a3 = o;
            }
            *(__half2*)(C + (size_t)gm * DIM + gc)       = __floats2half2_rn(a0, a1);
            *(__half2*)(C + (size_t)(gm + 8) * DIM + gc) = __floats2half2_rn(a2, a3);
        }
    }
}

// ---------------- output projection GEMM (fp32 epilogue) ---------------------
__global__ __launch_bounds__(256, 2) void gemm_out(
    const __half* __restrict__ A, const __half* __restrict__ B, float* __restrict__ C)
{
    extern __shared__ char smem[];
    uint32_t sm0 = smem_u32(smem);
    int tid = threadIdx.x, wid = tid >> 5, lane = tid & 31;
    int bm = blockIdx.y * 128, bn = blockIdx.x * 128;

    float acc[4][4][4];
    #pragma unroll
    for (int i = 0; i < 4; i++)
        #pragma unroll
        for (int j = 0; j < 4; j++)
            #pragma unroll
            for (int e = 0; e < 4; e++) acc[i][j][e] = 0.f;

    gemm_mainloop(sm0, tid, wid, lane, A, B, bm, bn, acc);

    int wm = wid >> 2, wn = wid & 3;
    int r = lane >> 2, cp = (lane & 3) * 2;
    #pragma unroll
    for (int mt = 0; mt < 4; mt++) {
        int gm = bm + wm * 64 + mt * 16 + r;
        #pragma unroll
        for (int nt = 0; nt < 4; nt++) {
            int gc = bn + wn * 32 + nt * 8 + cp;
            *(float2*)(C + (size_t)gm * DIM + gc)       = make_float2(acc[mt][nt][0], acc[mt][nt][1]);
            *(float2*)(C + (size_t)(gm + 8) * DIM + gc) = make_float2(acc[mt][nt][2], acc[mt][nt][3]);
        }
    }
}

// ---------------- HMMA fp16 1-pass causal flash attention --------------------
// 256 threads, 8 warps; CTA covers 128 q rows sharing each 64-key K/V stage.
#define FROW   144
#define FTILE  (64 * FROW)            // 9216
#define FSTAGE (2 * FTILE)            // 18432 (K, V)
#define FQOFF  (2 * FSTAGE)           // 36864
#define QTILE  (128 * FROW)           // 18432
#define FSMEM  (FQOFF + QTILE)        // 55296

__device__ __forceinline__ void flash_load_kv(
    uint32_t sbase,
    const __half* __restrict__ k, const __half* __restrict__ v,
    int grow0, int h, int tid)
{
    const __half* srcs[2] = { k, v };
    #pragma unroll
    for (int t = 0; t < 4; t++) {
        int i = tid + t * 256;          // 0..1023
        int tile = i >> 9;
        int r = (i >> 3) & 63;
        int ch = i & 7;
        uint32_t dst = sbase + tile * FTILE + r * FROW + ch * 16;
        cp_async16(dst, srcs[tile] + ((size_t)(grow0 + r) * DIM + h * DHEAD + ch * 8));
    }
}

__global__ __launch_bounds__(256) void flash_tc(
    const __half* __restrict__ Q, const __half* __restrict__ K,
    const __half* __restrict__ V, __half* __restrict__ O)
{
    extern __shared__ char smem[];
    uint32_t sm0 = smem_u32(smem);
    int tid = threadIdx.x, w = tid >> 5, lane = tid & 31;
    int bh = blockIdx.x;
    int b  = bh >> 4, h = bh & 15;
    int r0 = ((int)gridDim.y - 1 - (int)blockIdx.y) * 128;   // 128 q rows per CTA
    int ntiles = r0 / 64 + 2;
    int growq = b * N_TOK + r0;

    {   // Q (128 rows) + KV stage 0, then KV stage 1
        #pragma unroll
        for (int t = 0; t < 4; t++) {
            int i = tid + t * 256;      // 0..1023
            int r = i >> 3;
            int ch = i & 7;
            uint32_t dst = sm0 + FQOFF + r * FROW + ch * 16;
            cp_async16(dst, Q + ((size_t)(growq + r) * DIM + h * DHEAD + ch * 8));
        }
        flash_load_kv(sm0, K, V, b * N_TOK, h, tid);
        CP_COMMIT();
        flash_load_kv(sm0 + FSTAGE, K, V, b * N_TOK + 64, h, tid);
        CP_COMMIT();
    }

    uint32_t qf[4][4];
    float oacc[8][4];
    #pragma unroll
    for (int nt = 0; nt < 8; nt++)
        #pragma unroll
        for (int e = 0; e < 4; e++) oacc[nt][e] = 0.f;
    float m0 = -1e30f, m1 = -1e30f, l0 = 0.f, l1 = 0.f;
    int wmin = r0 + w * 16;             // this warp's MIN q row (mask gate)

    for (int t = 0; t < ntiles; t++) {
        if (t + 1 < ntiles) { CP_WAIT1(); } else { CP_WAIT0(); }
        __syncthreads();

        if (t == 0) {   // Q fragments (once); warp w covers q rows w*16..w*16+15
            uint32_t qb = sm0 + FQOFF + (uint32_t)((w * 16 + (lane & 15)) * FROW + (lane >> 4) * 16);
            #pragma unroll
            for (int kt = 0; kt < 4; kt++)
                ldmatrix_x4(qf[kt][0], qf[kt][1], qf[kt][2], qf[kt][3], qb + kt * 32);
        }

        uint32_t sb = sm0 + (uint32_t)(t & 1) * FSTAGE;

        float sacc[8][4];
        #pragma unroll
        for (int nt = 0; nt < 8; nt++)
            #pragma unroll
            for (int e = 0; e < 4; e++) sacc[nt][e] = 0.f;

        uint32_t kb = sb + (uint32_t)(((lane & 7) + ((lane >> 4) & 1) * 8) * FROW + ((lane >> 3) & 1) * 16);
        #pragma unroll
        for (int kt = 0; kt < 4; kt++)
            #pragma unroll
            for (int jg = 0; jg < 4; jg++) {
                uint32_t addr = kb + (uint32_t)(jg * 16 * FROW + kt * 32);
                uint32_t bhh[4];
                ldmatrix_x4(bhh[0], bhh[1], bhh[2], bhh[3], addr);
                mma_f16(sacc[2 * jg],     qf[kt], &bhh[0]);
                mma_f16(sacc[2 * jg + 1], qf[kt], &bhh[2]);
            }

        if (t * 64 + 63 > wmin) {   // mask any tile whose keys can exceed this warp's rows
            int i0 = r0 + w * 16 + (lane >> 2);
            int j0 = t * 64 + (lane & 3) * 2;
            #pragma unroll
            for (int nt = 0; nt < 8; nt++) {
                int jc = j0 + nt * 8;
                if (jc     > i0)     sacc[nt][0] = -1e30f;
                if (jc + 1 > i0)     sacc[nt][1] = -1e30f;
                if (jc     > i0 + 8) sacc[nt][2] = -1e30f;
                if (jc + 1 > i0 + 8) sacc[nt][3] = -1e30f;
            }
        }

        float mx0 = -1e30f, mx1 = -1e30f;
        #pragma unroll
        for (int nt = 0; nt < 8; nt++) {
            mx0 = fmaxf(mx0, fmaxf(sacc[nt][0], sacc[nt][1]));
            mx1 = fmaxf(mx1, fmaxf(sacc[nt][2], sacc[nt][3]));
        }
        mx0 = fmaxf(mx0, __shfl_xor_sync(0xFFFFFFFFu, mx0, 1));
        mx0 = fmaxf(mx0, __shfl_xor_sync(0xFFFFFFFFu, mx0, 2));
        mx1 = fmaxf(mx1, __shfl_xor_sync(0xFFFFFFFFu, mx1, 1));
        mx1 = fmaxf(mx1, __shfl_xor_sync(0xFFFFFFFFu, mx1, 2));
        float mn0 = fmaxf(m0, mx0), mn1 = fmaxf(m1, mx1);
        float sc0 = __expf(m0 - mn0), sc1 = __expf(m1 - mn1);
        l0 *= sc0; l1 *= sc1;
        #pragma unroll
        for (int nt = 0; nt < 8; nt++) {
            oacc[nt][0] *= sc0; oacc[nt][1] *= sc0;
            oacc[nt][2] *= sc1; oacc[nt][3] *= sc1;
        }
        float su0 = 0.f, su1 = 0.f;
        #pragma unroll
        for (int nt = 0; nt < 8; nt++) {
            float p0 = __expf(sacc[nt][0] - mn0);
            float p1 = __expf(sacc[nt][1] - mn0);
            float p2 = __expf(sacc[nt][2] - mn1);
            float p3 = __expf(sacc[nt][3] - mn1);
            sacc[nt][0] = p0; sacc[nt][1] = p1; sacc[nt][2] = p2; sacc[nt][3] = p3;
            su0 += p0 + p1; su1 += p2 + p3;
        }
        su0 += __shfl_xor_sync(0xFFFFFFFFu, su0, 1);
        su0 += __shfl_xor_sync(0xFFFFFFFFu, su0, 2);
        su1 += __shfl_xor_sync(0xFFFFFFFFu, su1, 1);
        su1 += __shfl_xor_sync(0xFFFFFFFFu, su1, 2);
        l0 += su0; l1 += su1;
        m0 = mn0; m1 = mn1;

        uint32_t vb = sb + FTILE
                    + (uint32_t)(((lane & 7) + ((lane >> 3) & 1) * 8) * FROW + ((lane >> 4) & 1) * 16);
        #pragma unroll
        for (int kt = 0; kt < 4; kt++) {
            int t0 = 2 * kt, t1 = 2 * kt + 1;
            uint32_t pa[4];
            pa[0] = pack_h2(sacc[t0][0], sacc[t0][1]);
            pa[1] = pack_h2(sacc[t0][2], sacc[t0][3]);
            pa[2] = pack_h2(sacc[t1][0], sacc[t1][1]);
            pa[3] = pack_h2(sacc[t1][2], sacc[t1][3]);
            #pragma unroll
            for (int dp = 0; dp < 4; dp++) {
                uint32_t addr = vb + (uint32_t)(kt * 16 * FROW + dp * 32);
                uint32_t vhh[4];
                ldmatrix_x4_trans(vhh[0], vhh[1], vhh[2], vhh[3], addr);
                mma_f16(oacc[2 * dp],     pa, &vhh[0]);
                mma_f16(oacc[2 * dp + 1], pa, &vhh[2]);
            }
        }

        __syncthreads();
        if (t + 2 < ntiles) {
            flash_load_kv(sm0 + (uint32_t)(t & 1) * FSTAGE, K, V,
                          b * N_TOK + (t + 2) * 64, h, tid);
            CP_COMMIT();
        }
    }

    float inv0 = 1.f / l0, inv1 = 1.f / l1;
    int gr = b * N_TOK + r0 + w * 16 + (lane >> 2);
    int gc = h * DHEAD + (lane & 3) * 2;
    #pragma unroll
    for (int nt = 0; nt < 8; nt++) {
        size_t o0 = (size_t)gr * DIM + gc + nt * 8;
        size_t o1 = (size_t)(gr + 8) * DIM + gc + nt * 8;
        *(__half2*)&O[o0] = __floats2half2_rn(oacc[nt][0] * inv0, oacc[nt][1] * inv0);
        *(__half2*)&O[o1] = __floats2half2_rn(oacc[nt][2] * inv1, oacc[nt][3] * inv1);
    }
}

// ---------------- launch -----------------------------------------------------
extern "C" void kernel_launch(void* const* d_in, const int* in_sizes, int n_in,
                              void* d_out, int out_size)
{
    const float* tokens = (const float*)d_in[0];
    const float* normw  = (const float*)d_in[1];
    const float* wq     = (const float*)d_in[2];
    const float* wk     = (const float*)d_in[3];
    const float* wv     = (const float*)d_in[4];
    const float* wo     = (const float*)d_in[5];
    float* out = (float*)d_out;

    __half *x, *q, *k, *v, *ao;
    __half *pwq, *pwk, *pwv, *pwo;
    cudaGetSymbolAddress((void**)&x,   g_x);
    cudaGetSymbolAddress((void**)&q,   g_q);
    cudaGetSymbolAddress((void**)&k,   g_k);
    cudaGetSymbolAddress((void**)&v,   g_v);
    cudaGetSymbolAddress((void**)&ao,  g_ao);
    cudaGetSymbolAddress((void**)&pwq, g_wq);
    cudaGetSymbolAddress((void**)&pwk, g_wk);
    cudaGetSymbolAddress((void**)&pwv, g_wv);
    cudaGetSymbolAddress((void**)&pwo, g_wo);

    cudaFuncSetAttribute(gemm_qkv, cudaFuncAttributeMaxDynamicSharedMemorySize, GSMEM_DYN);
    cudaFuncSetAttribute(gemm_out, cudaFuncAttributeMaxDynamicSharedMemorySize, GSMEM_DYN);
    cudaFuncSetAttribute(flash_tc, cudaFuncAttributeMaxDynamicSharedMemorySize, FSMEM);

    rope_table_kernel<<<256, 256>>>();                                    // 1
    split_w4_kernel<<<4096, 256>>>(wq, wk, wv, wo, pwq, pwk, pwv, pwo);   // 2
    rmsnorm_kernel<<<MROWS, 256>>>(tokens, normw);                        // 3

    gemm_qkv<<<dim3(24, MROWS / 128), 256, GSMEM_DYN>>>(                  // 4
        x, pwq, pwk, pwv, q, k, v);

    flash_tc<<<dim3(BATCH * NHEAD, N_TOK / 128), 256, FSMEM>>>(           // 5
        q, k, v, ao);

    gemm_out<<<dim3(DIM / 128, MROWS / 128), 256, GSMEM_DYN>>>(           // 6
        ao, pwo, out);
}